// round 1
// baseline (speedup 1.0000x reference)
#include <cuda_runtime.h>
#include <math.h>

// Problem constants
#define BSZ   8192
#define DIN   2048
#define H0D   1024
#define H1D   512
#define LATD  128
#define NC    8

// GEMM tiling
#define BM 128
#define BN 128
#define BK 16
#define TM 8
#define TN 8
#define NTHREADS 256

// Scratch (device globals — no allocation allowed)
__device__ float g_h0[(size_t)BSZ * H0D];   // h0, later reused as d1
__device__ float g_h1[(size_t)BSZ * H1D];   // h1, later reused as d0
__device__ float g_z [(size_t)BSZ * LATD];
__device__ int   g_perm[NC * BSZ];
__device__ int   g_counts[NC];

// ---------------------------------------------------------------------------
// cluster routing: histogram + scatter of row indices by label
// ---------------------------------------------------------------------------
__global__ void reset_counts_k() {
    if (threadIdx.x < NC) g_counts[threadIdx.x] = 0;
}

__global__ void scatter_k(const int* __restrict__ labels) {
    int b = blockIdx.x * blockDim.x + threadIdx.x;
    if (b < BSZ) {
        int c = labels[b];
        int p = atomicAdd(&g_counts[c], 1);
        g_perm[c * BSZ + p] = b;
    }
}

// ---------------------------------------------------------------------------
// Plain GEMM: Out[m,n] = act( sum_k A[m,k] * W[k,n] + bias[n] )
// A: [M,K] row-major, W: [K,N] row-major. M % BM == 0, N % BN == 0, K % BK == 0.
// ---------------------------------------------------------------------------
template <bool RELU>
__global__ __launch_bounds__(NTHREADS)
void gemm_k(const float* __restrict__ A, const float* __restrict__ W,
            const float* __restrict__ bias, float* __restrict__ Out,
            int N, int K) {
    __shared__ float As[BK][BM];
    __shared__ float Bs[BK][BN];

    const int tid = threadIdx.x;
    const int tx = tid & 15;        // 0..15 -> 8 cols each
    const int ty = tid >> 4;        // 0..15 -> 8 rows each
    const int m0 = blockIdx.y * BM;
    const int n0 = blockIdx.x * BN;

    const float* Aptr = A + (size_t)m0 * K;
    const float* Wptr = W + n0;

    float acc[TM][TN];
    #pragma unroll
    for (int i = 0; i < TM; i++)
        #pragma unroll
        for (int j = 0; j < TN; j++) acc[i][j] = 0.f;

    for (int k0 = 0; k0 < K; k0 += BK) {
        // Load A tile (BM x BK = 512 float4), transpose into As[k][m]
        #pragma unroll
        for (int i = 0; i < 2; i++) {
            int idx = tid + i * NTHREADS;
            int row = idx >> 2;
            int c4  = idx & 3;
            float4 v = *reinterpret_cast<const float4*>(Aptr + (size_t)row * K + k0 + c4 * 4);
            As[c4 * 4 + 0][row] = v.x;
            As[c4 * 4 + 1][row] = v.y;
            As[c4 * 4 + 2][row] = v.z;
            As[c4 * 4 + 3][row] = v.w;
        }
        // Load W tile (BK x BN = 512 float4)
        #pragma unroll
        for (int i = 0; i < 2; i++) {
            int idx = tid + i * NTHREADS;
            int row = idx >> 5;
            int c4  = idx & 31;
            float4 v = *reinterpret_cast<const float4*>(Wptr + (size_t)(k0 + row) * N + c4 * 4);
            *reinterpret_cast<float4*>(&Bs[row][c4 * 4]) = v;
        }
        __syncthreads();

        #pragma unroll
        for (int k = 0; k < BK; k++) {
            float ra[TM], rb[TN];
            #pragma unroll
            for (int i = 0; i < TM; i++) ra[i] = As[k][ty * TM + i];
            #pragma unroll
            for (int j = 0; j < TN; j++) rb[j] = Bs[k][tx * TN + j];
            #pragma unroll
            for (int i = 0; i < TM; i++)
                #pragma unroll
                for (int j = 0; j < TN; j++)
                    acc[i][j] = fmaf(ra[i], rb[j], acc[i][j]);
        }
        __syncthreads();
    }

    // Epilogue: bias + optional ReLU, vectorized stores
    #pragma unroll
    for (int i = 0; i < TM; i++) {
        int m = m0 + ty * TM + i;
        float* orow = Out + (size_t)m * N + n0 + tx * TN;
        #pragma unroll
        for (int j4 = 0; j4 < 2; j4++) {
            float4 v;
            float* a = &acc[i][j4 * 4];
            const float* bp = bias + n0 + tx * TN + j4 * 4;
            v.x = a[0] + bp[0]; v.y = a[1] + bp[1];
            v.z = a[2] + bp[2]; v.w = a[3] + bp[3];
            if (RELU) {
                v.x = fmaxf(v.x, 0.f); v.y = fmaxf(v.y, 0.f);
                v.z = fmaxf(v.z, 0.f); v.w = fmaxf(v.w, 0.f);
            }
            *reinterpret_cast<float4*>(orow + j4 * 4) = v;
        }
    }
}

// ---------------------------------------------------------------------------
// Grouped GEMM (per-cluster weights) with row gather/scatter via g_perm.
// Wg: [NC, K, N], bg: [NC, N]. grid.z = cluster id.
// ---------------------------------------------------------------------------
template <bool RELU>
__global__ __launch_bounds__(NTHREADS)
void ggemm_k(const float* __restrict__ A, const float* __restrict__ Wg,
             const float* __restrict__ bg, float* __restrict__ Out,
             int N, int K) {
    const int c   = blockIdx.z;
    const int cnt = g_counts[c];
    const int m0  = blockIdx.y * BM;
    if (m0 >= cnt) return;

    __shared__ float As[BK][BM];
    __shared__ float Bs[BK][BN];
    __shared__ int   rows_s[BM];

    const int tid = threadIdx.x;
    const int tx = tid & 15;
    const int ty = tid >> 4;
    const int n0 = blockIdx.x * BN;

    if (tid < BM) {
        int r = m0 + tid;
        rows_s[tid] = (r < cnt) ? g_perm[c * BSZ + r] : -1;
    }
    __syncthreads();

    const float* W    = Wg + (size_t)c * K * N + n0;
    const float* bias = bg + (size_t)c * N;

    float acc[TM][TN];
    #pragma unroll
    for (int i = 0; i < TM; i++)
        #pragma unroll
        for (int j = 0; j < TN; j++) acc[i][j] = 0.f;

    for (int k0 = 0; k0 < K; k0 += BK) {
        #pragma unroll
        for (int i = 0; i < 2; i++) {
            int idx = tid + i * NTHREADS;
            int row = idx >> 2;
            int c4  = idx & 3;
            int grow = rows_s[row];
            float4 v = make_float4(0.f, 0.f, 0.f, 0.f);
            if (grow >= 0)
                v = *reinterpret_cast<const float4*>(A + (size_t)grow * K + k0 + c4 * 4);
            As[c4 * 4 + 0][row] = v.x;
            As[c4 * 4 + 1][row] = v.y;
            As[c4 * 4 + 2][row] = v.z;
            As[c4 * 4 + 3][row] = v.w;
        }
        #pragma unroll
        for (int i = 0; i < 2; i++) {
            int idx = tid + i * NTHREADS;
            int row = idx >> 5;
            int c4  = idx & 31;
            float4 v = *reinterpret_cast<const float4*>(W + (size_t)(k0 + row) * N + c4 * 4);
            *reinterpret_cast<float4*>(&Bs[row][c4 * 4]) = v;
        }
        __syncthreads();

        #pragma unroll
        for (int k = 0; k < BK; k++) {
            float ra[TM], rb[TN];
            #pragma unroll
            for (int i = 0; i < TM; i++) ra[i] = As[k][ty * TM + i];
            #pragma unroll
            for (int j = 0; j < TN; j++) rb[j] = Bs[k][tx * TN + j];
            #pragma unroll
            for (int i = 0; i < TM; i++)
                #pragma unroll
                for (int j = 0; j < TN; j++)
                    acc[i][j] = fmaf(ra[i], rb[j], acc[i][j]);
        }
        __syncthreads();
    }

    #pragma unroll
    for (int i = 0; i < TM; i++) {
        int grow = rows_s[ty * TM + i];
        if (grow < 0) continue;
        float* orow = Out + (size_t)grow * N + n0 + tx * TN;
        #pragma unroll
        for (int j4 = 0; j4 < 2; j4++) {
            float4 v;
            float* a = &acc[i][j4 * 4];
            const float* bp = bias + n0 + tx * TN + j4 * 4;
            v.x = a[0] + bp[0]; v.y = a[1] + bp[1];
            v.z = a[2] + bp[2]; v.w = a[3] + bp[3];
            if (RELU) {
                v.x = fmaxf(v.x, 0.f); v.y = fmaxf(v.y, 0.f);
                v.z = fmaxf(v.z, 0.f); v.w = fmaxf(v.w, 0.f);
            }
            *reinterpret_cast<float4*>(orow + j4 * 4) = v;
        }
    }
}

// ---------------------------------------------------------------------------
// Reparameterize: z = mu + eps * exp(0.5 * logvar)
// ---------------------------------------------------------------------------
__global__ void z_k(const float* __restrict__ mu, const float* __restrict__ logvar,
                    const float* __restrict__ eps, float* __restrict__ z, int n) {
    int i = blockIdx.x * blockDim.x + threadIdx.x;
    if (i < n) z[i] = fmaf(eps[i], expf(0.5f * logvar[i]), mu[i]);
}

// ---------------------------------------------------------------------------
// Launcher
// ---------------------------------------------------------------------------
extern "C" void kernel_launch(void* const* d_in, const int* in_sizes, int n_in,
                              void* d_out, int out_size) {
    const float* x        = (const float*)d_in[0];
    const int*   labels   = (const int*)  d_in[1];
    const float* eps      = (const float*)d_in[2];
    const float* W_enc0   = (const float*)d_in[3];
    const float* b_enc0   = (const float*)d_in[4];
    const float* W_enc1   = (const float*)d_in[5];
    const float* b_enc1   = (const float*)d_in[6];
    const float* W_mu     = (const float*)d_in[7];
    const float* b_mu     = (const float*)d_in[8];
    const float* W_logvar = (const float*)d_in[9];
    const float* b_logvar = (const float*)d_in[10];
    const float* W_dec0   = (const float*)d_in[11];
    const float* b_dec0   = (const float*)d_in[12];
    const float* W_dec1   = (const float*)d_in[13];
    const float* b_dec1   = (const float*)d_in[14];
    const float* W_out    = (const float*)d_in[15];
    const float* b_out    = (const float*)d_in[16];

    float* recon  = (float*)d_out;                       // [B, DIN]
    float* mu     = recon + (size_t)BSZ * DIN;           // [B, LAT]
    float* logvar = mu    + (size_t)BSZ * LATD;          // [B, LAT]

    float *h0p, *h1p, *zp;
    cudaGetSymbolAddress((void**)&h0p, g_h0);
    cudaGetSymbolAddress((void**)&h1p, g_h1);
    cudaGetSymbolAddress((void**)&zp,  g_z);

    // 1. cluster routing
    reset_counts_k<<<1, 32>>>();
    scatter_k<<<BSZ / 256, 256>>>(labels);

    // 2. enc0 (grouped): h0 = relu(x @ W_enc0[c] + b_enc0[c])   [B, H0]
    ggemm_k<true><<<dim3(H0D / BN, BSZ / BM, NC), NTHREADS>>>(
        x, W_enc0, b_enc0, h0p, H0D, DIN);

    // 3. enc1: h1 = relu(h0 @ W_enc1 + b_enc1)                  [B, H1]
    gemm_k<true><<<dim3(H1D / BN, BSZ / BM), NTHREADS>>>(
        h0p, W_enc1, b_enc1, h1p, H1D, H0D);

    // 4. heads: mu / logvar straight into d_out                 [B, LAT] each
    gemm_k<false><<<dim3(LATD / BN, BSZ / BM), NTHREADS>>>(
        h1p, W_mu, b_mu, mu, LATD, H1D);
    gemm_k<false><<<dim3(LATD / BN, BSZ / BM), NTHREADS>>>(
        h1p, W_logvar, b_logvar, logvar, LATD, H1D);

    // 5. reparameterize
    z_k<<<(BSZ * LATD) / 256, 256>>>(mu, logvar, eps, zp, BSZ * LATD);

    // 6. dec0: d0 = relu(z @ W_dec0 + b_dec0)  (reuse g_h1)     [B, H1]
    gemm_k<true><<<dim3(H1D / BN, BSZ / BM), NTHREADS>>>(
        zp, W_dec0, b_dec0, h1p, H1D, LATD);

    // 7. dec1 (grouped): d1 = relu(d0 @ W_dec1[c] + b_dec1[c]) (reuse g_h0)
    ggemm_k<true><<<dim3(H0D / BN, BSZ / BM, NC), NTHREADS>>>(
        h1p, W_dec1, b_dec1, h0p, H0D, H1D);

    // 8. out: recon = d1 @ W_out + b_out                        [B, DIN]
    gemm_k<false><<<dim3(DIN / BN, BSZ / BM), NTHREADS>>>(
        h0p, W_out, b_out, recon, DIN, H0D);
}

// round 4
// speedup vs baseline: 2.0045x; 2.0045x over previous
#include <cuda_runtime.h>
#include <cuda_bf16.h>
#include <cstdint>
#include <math.h>

// ---------------------------------------------------------------------------
// Problem constants
// ---------------------------------------------------------------------------
#define BSZ   8192
#define DIN   2048
#define H0D   1024
#define H1D   512
#define LATD  128
#define NC    8

typedef __nv_bfloat16 bf16;

// ---------------------------------------------------------------------------
// Scratch (device globals)
// ---------------------------------------------------------------------------
__device__ bf16 g_xh [(size_t)BSZ * DIN];
__device__ bf16 g_xl [(size_t)BSZ * DIN];
__device__ bf16 g_w0h[(size_t)NC * H0D * DIN];   // enc0^T [C, H0, DIN]
__device__ bf16 g_w0l[(size_t)NC * H0D * DIN];
__device__ bf16 g_w1h[(size_t)H1D * H0D];        // enc1^T [H1, H0]
__device__ bf16 g_w1l[(size_t)H1D * H0D];
__device__ bf16 g_wd1h[(size_t)NC * H0D * H1D];  // dec1^T [C, H0, H1]
__device__ bf16 g_wd1l[(size_t)NC * H0D * H1D];
__device__ bf16 g_woh[(size_t)DIN * H0D];        // out^T [DIN, H0]
__device__ bf16 g_wol[(size_t)DIN * H0D];
__device__ bf16 g_h0h[(size_t)BSZ * H0D];        // h0, reused as d1
__device__ bf16 g_h0l[(size_t)BSZ * H0D];
__device__ bf16 g_d0h[(size_t)BSZ * H1D];
__device__ bf16 g_d0l[(size_t)BSZ * H1D];
__device__ float g_h1[(size_t)BSZ * H1D];
__device__ float g_z [(size_t)BSZ * LATD];
__device__ int   g_perm[NC * BSZ];
__device__ int   g_counts[NC];

// ---------------------------------------------------------------------------
// Routing
// ---------------------------------------------------------------------------
__global__ void reset_counts_k() {
    if (threadIdx.x < NC) g_counts[threadIdx.x] = 0;
}
__global__ void scatter_k(const int* __restrict__ labels) {
    int b = blockIdx.x * blockDim.x + threadIdx.x;
    if (b < BSZ) {
        int c = labels[b];
        int p = atomicAdd(&g_counts[c], 1);
        g_perm[c * BSZ + p] = b;
    }
}

// ---------------------------------------------------------------------------
// fp32 -> bf16 hi/lo split
// ---------------------------------------------------------------------------
__device__ __forceinline__ void split_bf16(float v, bf16& h, bf16& l) {
    h = __float2bfloat16_rn(v);
    l = __float2bfloat16_rn(v - __bfloat162float(h));
}

__global__ void convert_act_k(const float* __restrict__ X,
                              bf16* __restrict__ H, bf16* __restrict__ L, int n4) {
    int i = blockIdx.x * blockDim.x + threadIdx.x;
    if (i >= n4) return;
    float4 v = reinterpret_cast<const float4*>(X)[i];
    bf16 h0, h1, h2, h3, l0, l1, l2, l3;
    split_bf16(v.x, h0, l0); split_bf16(v.y, h1, l1);
    split_bf16(v.z, h2, l2); split_bf16(v.w, h3, l3);
    __nv_bfloat162 ph0 = __halves2bfloat162(h0, h1);
    __nv_bfloat162 ph1 = __halves2bfloat162(h2, h3);
    __nv_bfloat162 pl0 = __halves2bfloat162(l0, l1);
    __nv_bfloat162 pl1 = __halves2bfloat162(l2, l3);
    uint2 uh = make_uint2(*(uint32_t*)&ph0, *(uint32_t*)&ph1);
    uint2 ul = make_uint2(*(uint32_t*)&pl0, *(uint32_t*)&pl1);
    *reinterpret_cast<uint2*>(H + (size_t)i * 4) = uh;
    *reinterpret_cast<uint2*>(L + (size_t)i * 4) = ul;
}

// Weight convert + transpose: W [K,N] fp32 -> Th/Tl [N,K] bf16. grid.z = group.
__global__ void convert_wt_k(const float* __restrict__ W,
                             bf16* __restrict__ Th, bf16* __restrict__ Tl,
                             int K, int N) {
    __shared__ float tile[32][33];
    int g = blockIdx.z;
    const float* Wg = W + (size_t)g * K * N;
    bf16* Thg = Th + (size_t)g * N * K;
    bf16* Tlg = Tl + (size_t)g * N * K;
    int n0 = blockIdx.x * 32, k0 = blockIdx.y * 32;
    int tx = threadIdx.x, ty = threadIdx.y;   // 32 x 8
    #pragma unroll
    for (int i = 0; i < 4; i++)
        tile[ty + 8 * i][tx] = Wg[(size_t)(k0 + ty + 8 * i) * N + n0 + tx];
    __syncthreads();
    #pragma unroll
    for (int i = 0; i < 4; i++) {
        float v = tile[tx][ty + 8 * i];
        bf16 h, l;
        split_bf16(v, h, l);
        size_t o = (size_t)(n0 + ty + 8 * i) * K + k0 + tx;
        Thg[o] = h;
        Tlg[o] = l;
    }
}

// ---------------------------------------------------------------------------
// PTX wrappers (all sm_80-compatible)
// ---------------------------------------------------------------------------
__device__ __forceinline__ uint32_t smem_u32(const void* p) {
    uint32_t a;
    asm("{ .reg .u64 t; cvta.to.shared.u64 t, %1; cvt.u32.u64 %0, t; }"
        : "=r"(a) : "l"(p));
    return a;
}

__device__ __forceinline__ void cp_async16(uint32_t saddr, const void* g, bool ok) {
    int sz = ok ? 16 : 0;
    asm volatile("cp.async.cg.shared.global [%0], [%1], 16, %2;"
                 :: "r"(saddr), "l"(g), "r"(sz));
}
#define CP_COMMIT() asm volatile("cp.async.commit_group;" ::: "memory")
#define CP_WAIT(n)  asm volatile("cp.async.wait_group %0;" :: "n"(n) : "memory")

__device__ __forceinline__ void ldsm_x4(uint32_t* r, uint32_t addr) {
    asm volatile("ldmatrix.sync.aligned.m8n8.x4.shared.b16 {%0,%1,%2,%3}, [%4];"
                 : "=r"(r[0]), "=r"(r[1]), "=r"(r[2]), "=r"(r[3]) : "r"(addr));
}

__device__ __forceinline__ void mma16816(float* c, const uint32_t* a, const uint32_t* b) {
    asm volatile(
        "mma.sync.aligned.m16n8k16.row.col.f32.bf16.bf16.f32 "
        "{%0,%1,%2,%3}, {%4,%5,%6,%7}, {%8,%9}, {%0,%1,%2,%3};"
        : "+f"(c[0]), "+f"(c[1]), "+f"(c[2]), "+f"(c[3])
        : "r"(a[0]), "r"(a[1]), "r"(a[2]), "r"(a[3]), "r"(b[0]), "r"(b[1]));
}

// ---------------------------------------------------------------------------
// mma.sync GEMM: 128x128x32 CTA tile, bf16x3 split, cp.async double buffer
// smem tile layout: rows of 32 bf16 padded to 40 (80 bytes) -> conflict-free
// ldmatrix (16B phases: 0,5,2,7,4,1,6,3).
// ---------------------------------------------------------------------------
#define TC_BM 128
#define TC_BN 128
#define TC_KC 32
#define TC_THREADS 256
#define ROWB 80                       // bytes per smem row
#define TILEB (128 * ROWB)            // 10240 B per matrix tile
#define STAGEB (4 * TILEB)            // Ah, Al, Bh, Bl
#define SM_ROWS_OFF (2 * STAGEB)      // rows_s after 2 stages
#define TC_SMEM_TOTAL (SM_ROWS_OFF + 128 * 4)

template <bool GROUPED>
__device__ __forceinline__ void tc_load_stage(
    uint32_t sb, const int* __restrict__ rows, int tid, int stage, int k0,
    const bf16* __restrict__ Ah, const bf16* __restrict__ Al,
    const bf16* __restrict__ Bh, const bf16* __restrict__ Bl,
    int m0, int n0, int K)
{
    uint32_t base = sb + stage * STAGEB;
    #pragma unroll
    for (int t = 0; t < 4; t++) {
        int idx  = tid + t * TC_THREADS;   // 0..1023
        int half = idx >> 9;               // 0: hi, 1: lo
        int rem  = idx & 511;
        int row  = rem >> 2;
        int v    = rem & 3;
        uint32_t soff = (uint32_t)(row * ROWB + v * 16);
        // A (gathered if grouped)
        int gr = GROUPED ? rows[row] : (m0 + row);
        bool ok = !GROUPED || (gr >= 0);
        const bf16* asrc = half ? Al : Ah;
        cp_async16(base + half * TILEB + soff,
                   asrc + ((size_t)(ok ? gr : 0) * K + k0 + v * 8), ok);
        // B (weights, [N,K])
        const bf16* bsrc = half ? Bl : Bh;
        cp_async16(base + 2 * TILEB + half * TILEB + soff,
                   bsrc + ((size_t)(n0 + row) * K + k0 + v * 8), true);
    }
}

// OUTMODE: 0 = fp32 Out, 1 = bf16 hi/lo Oh/Ol
template <bool RELU, bool GROUPED, int OUTMODE>
__global__ void __launch_bounds__(TC_THREADS, 2)
tc_gemm_k(const bf16* __restrict__ Ah, const bf16* __restrict__ Al,
          const bf16* __restrict__ Bhg, const bf16* __restrict__ Blg,
          const float* __restrict__ biasg,
          float* __restrict__ OutF,
          bf16* __restrict__ Oh, bf16* __restrict__ Ol,
          int M, int N, int K)
{
    extern __shared__ char smem[];
    const int tid  = threadIdx.x;
    const int wid  = tid >> 5;
    const int lane = tid & 31;
    const int wm   = wid >> 2;   // 0..1
    const int wn   = wid & 3;    // 0..3
    const int g    = GROUPED ? blockIdx.z : 0;
    const int m0   = blockIdx.y * TC_BM;
    if (GROUPED) {
        if (m0 >= g_counts[g]) return;
    }
    const int n0 = blockIdx.x * TC_BN;
    uint32_t sb = smem_u32(smem);
    int* rows_s = reinterpret_cast<int*>(smem + SM_ROWS_OFF);

    if (GROUPED && tid < TC_BM) {
        int cnt = g_counts[g];
        int r = m0 + tid;
        rows_s[tid] = (r < cnt) ? g_perm[g * BSZ + r] : -1;
    }
    __syncthreads();

    const bf16* Bh = Bhg + (GROUPED ? (size_t)g * N * K : 0);
    const bf16* Bl = Blg + (GROUPED ? (size_t)g * N * K : 0);

    float acc[4][4][4];
    #pragma unroll
    for (int i = 0; i < 4; i++)
        #pragma unroll
        for (int j = 0; j < 4; j++)
            #pragma unroll
            for (int q = 0; q < 4; q++) acc[i][j][q] = 0.f;

    const int nchunks = K / TC_KC;

    tc_load_stage<GROUPED>(sb, rows_s, tid, 0, 0, Ah, Al, Bh, Bl, m0, n0, K);
    CP_COMMIT();

    for (int i = 0; i < nchunks; i++) {
        const int s = i & 1;
        if (i + 1 < nchunks) {
            tc_load_stage<GROUPED>(sb, rows_s, tid, s ^ 1, (i + 1) * TC_KC,
                                   Ah, Al, Bh, Bl, m0, n0, K);
            CP_COMMIT();
            CP_WAIT(1);
        } else {
            CP_WAIT(0);
        }
        __syncthreads();

        uint32_t stage = sb + s * STAGEB;
        #pragma unroll
        for (int kk = 0; kk < 2; kk++) {
            // B fragments (4 n8 tiles each for hi and lo)
            uint32_t bh[8], bl[8];
            #pragma unroll
            for (int p = 0; p < 2; p++) {
                uint32_t nrow = (uint32_t)(wn * 32 + p * 16 + (lane & 15));
                uint32_t off  = nrow * ROWB + kk * 32 + (lane >> 4) * 16;
                uint32_t r[4];
                ldsm_x4(r, stage + 2 * TILEB + off);
                bh[4 * p + 0] = r[0]; bh[4 * p + 1] = r[2];
                bh[4 * p + 2] = r[1]; bh[4 * p + 3] = r[3];
                ldsm_x4(r, stage + 3 * TILEB + off);
                bl[4 * p + 0] = r[0]; bl[4 * p + 1] = r[2];
                bl[4 * p + 2] = r[1]; bl[4 * p + 3] = r[3];
            }
            // A hi fragments
            uint32_t a[4][4];
            #pragma unroll
            for (int mt = 0; mt < 4; mt++) {
                uint32_t arow = (uint32_t)(wm * 64 + mt * 16 + (lane & 15));
                ldsm_x4(a[mt], stage + arow * ROWB + kk * 32 + (lane >> 4) * 16);
            }
            // pass hh and hl
            #pragma unroll
            for (int mt = 0; mt < 4; mt++)
                #pragma unroll
                for (int nt = 0; nt < 4; nt++) {
                    mma16816(acc[mt][nt], a[mt], &bh[2 * nt]);
                    mma16816(acc[mt][nt], a[mt], &bl[2 * nt]);
                }
            // A lo fragments (overwrite)
            #pragma unroll
            for (int mt = 0; mt < 4; mt++) {
                uint32_t arow = (uint32_t)(wm * 64 + mt * 16 + (lane & 15));
                ldsm_x4(a[mt], stage + TILEB + arow * ROWB + kk * 32 + (lane >> 4) * 16);
            }
            // pass lh
            #pragma unroll
            for (int mt = 0; mt < 4; mt++)
                #pragma unroll
                for (int nt = 0; nt < 4; nt++)
                    mma16816(acc[mt][nt], a[mt], &bh[2 * nt]);
        }
        __syncthreads();
    }

    // Epilogue
    const float* bias = biasg + (GROUPED ? (size_t)g * N : 0);
    #pragma unroll
    for (int mt = 0; mt < 4; mt++) {
        #pragma unroll
        for (int half = 0; half < 2; half++) {
            int rloc = wm * 64 + mt * 16 + (lane >> 2) + half * 8;
            int gm = GROUPED ? rows_s[rloc] : (m0 + rloc);
            if (GROUPED && gm < 0) continue;
            #pragma unroll
            for (int nt = 0; nt < 4; nt++) {
                int col = n0 + wn * 32 + nt * 8 + 2 * (lane & 3);
                float c0 = acc[mt][nt][2 * half + 0] + bias[col];
                float c1 = acc[mt][nt][2 * half + 1] + bias[col + 1];
                if (RELU) { c0 = fmaxf(c0, 0.f); c1 = fmaxf(c1, 0.f); }
                if (OUTMODE == 0) {
                    *reinterpret_cast<float2*>(OutF + (size_t)gm * N + col) =
                        make_float2(c0, c1);
                } else {
                    bf16 h0, h1, l0, l1;
                    split_bf16(c0, h0, l0);
                    split_bf16(c1, h1, l1);
                    __nv_bfloat162 ph = __halves2bfloat162(h0, h1);
                    __nv_bfloat162 pl = __halves2bfloat162(l0, l1);
                    *reinterpret_cast<uint32_t*>(Oh + (size_t)gm * N + col) =
                        *reinterpret_cast<uint32_t*>(&ph);
                    *reinterpret_cast<uint32_t*>(Ol + (size_t)gm * N + col) =
                        *reinterpret_cast<uint32_t*>(&pl);
                }
            }
        }
    }
}

// ---------------------------------------------------------------------------
// SIMT fp32 GEMM (small layers). OUTMODE: 0 = fp32, 1 = bf16 hi/lo
// ---------------------------------------------------------------------------
#define BM 128
#define BN 128
#define BK 16
#define TM 8
#define TN 8
#define NTHREADS 256

template <bool RELU, int OUTMODE>
__global__ __launch_bounds__(NTHREADS)
void gemm_k(const float* __restrict__ A, const float* __restrict__ W,
            const float* __restrict__ bias, float* __restrict__ Out,
            bf16* __restrict__ Oh, bf16* __restrict__ Ol,
            int N, int K) {
    __shared__ float As[BK][BM];
    __shared__ float Bs[BK][BN];

    const int tid = threadIdx.x;
    const int tx = tid & 15;
    const int ty = tid >> 4;
    const int m0 = blockIdx.y * BM;
    const int n0 = blockIdx.x * BN;

    const float* Aptr = A + (size_t)m0 * K;
    const float* Wptr = W + n0;

    float acc[TM][TN];
    #pragma unroll
    for (int i = 0; i < TM; i++)
        #pragma unroll
        for (int j = 0; j < TN; j++) acc[i][j] = 0.f;

    for (int k0 = 0; k0 < K; k0 += BK) {
        #pragma unroll
        for (int i = 0; i < 2; i++) {
            int idx = tid + i * NTHREADS;
            int row = idx >> 2;
            int c4  = idx & 3;
            float4 v = *reinterpret_cast<const float4*>(Aptr + (size_t)row * K + k0 + c4 * 4);
            As[c4 * 4 + 0][row] = v.x;
            As[c4 * 4 + 1][row] = v.y;
            As[c4 * 4 + 2][row] = v.z;
            As[c4 * 4 + 3][row] = v.w;
        }
        #pragma unroll
        for (int i = 0; i < 2; i++) {
            int idx = tid + i * NTHREADS;
            int row = idx >> 5;
            int c4  = idx & 31;
            float4 v = *reinterpret_cast<const float4*>(Wptr + (size_t)(k0 + row) * N + c4 * 4);
            *reinterpret_cast<float4*>(&Bs[row][c4 * 4]) = v;
        }
        __syncthreads();

        #pragma unroll
        for (int k = 0; k < BK; k++) {
            float ra[TM], rb[TN];
            #pragma unroll
            for (int i = 0; i < TM; i++) ra[i] = As[k][ty * TM + i];
            #pragma unroll
            for (int j = 0; j < TN; j++) rb[j] = Bs[k][tx * TN + j];
            #pragma unroll
            for (int i = 0; i < TM; i++)
                #pragma unroll
                for (int j = 0; j < TN; j++)
                    acc[i][j] = fmaf(ra[i], rb[j], acc[i][j]);
        }
        __syncthreads();
    }

    #pragma unroll
    for (int i = 0; i < TM; i++) {
        int m = m0 + ty * TM + i;
        size_t obase = (size_t)m * N + n0 + tx * TN;
        #pragma unroll
        for (int j = 0; j < TN; j++) {
            float v = acc[i][j] + bias[n0 + tx * TN + j];
            if (RELU) v = fmaxf(v, 0.f);
            acc[i][j] = v;
        }
        if (OUTMODE == 0) {
            #pragma unroll
            for (int j4 = 0; j4 < 2; j4++)
                *reinterpret_cast<float4*>(Out + obase + j4 * 4) =
                    make_float4(acc[i][j4*4], acc[i][j4*4+1], acc[i][j4*4+2], acc[i][j4*4+3]);
        } else {
            uint32_t* dh = reinterpret_cast<uint32_t*>(Oh + obase);
            uint32_t* dl = reinterpret_cast<uint32_t*>(Ol + obase);
            #pragma unroll
            for (int q = 0; q < 4; q++) {
                bf16 h0, h1, l0, l1;
                split_bf16(acc[i][2*q],   h0, l0);
                split_bf16(acc[i][2*q+1], h1, l1);
                __nv_bfloat162 ph = __halves2bfloat162(h0, h1);
                __nv_bfloat162 pl = __halves2bfloat162(l0, l1);
                dh[q] = *reinterpret_cast<uint32_t*>(&ph);
                dl[q] = *reinterpret_cast<uint32_t*>(&pl);
            }
        }
    }
}

// ---------------------------------------------------------------------------
// Reparameterize
// ---------------------------------------------------------------------------
__global__ void z_k(const float* __restrict__ mu, const float* __restrict__ logvar,
                    const float* __restrict__ eps, float* __restrict__ z, int n) {
    int i = blockIdx.x * blockDim.x + threadIdx.x;
    if (i < n) z[i] = fmaf(eps[i], expf(0.5f * logvar[i]), mu[i]);
}

// ---------------------------------------------------------------------------
// Launcher
// ---------------------------------------------------------------------------
extern "C" void kernel_launch(void* const* d_in, const int* in_sizes, int n_in,
                              void* d_out, int out_size) {
    const float* x        = (const float*)d_in[0];
    const int*   labels   = (const int*)  d_in[1];
    const float* eps      = (const float*)d_in[2];
    const float* W_enc0   = (const float*)d_in[3];
    const float* b_enc0   = (const float*)d_in[4];
    const float* W_enc1   = (const float*)d_in[5];
    const float* b_enc1   = (const float*)d_in[6];
    const float* W_mu     = (const float*)d_in[7];
    const float* b_mu     = (const float*)d_in[8];
    const float* W_logvar = (const float*)d_in[9];
    const float* b_logvar = (const float*)d_in[10];
    const float* W_dec0   = (const float*)d_in[11];
    const float* b_dec0   = (const float*)d_in[12];
    const float* W_dec1   = (const float*)d_in[13];
    const float* b_dec1   = (const float*)d_in[14];
    const float* W_out    = (const float*)d_in[15];
    const float* b_out    = (const float*)d_in[16];

    float* recon  = (float*)d_out;
    float* mu     = recon + (size_t)BSZ * DIN;
    float* logvar = mu    + (size_t)BSZ * LATD;

    bf16 *xh, *xl, *w0h, *w0l, *w1h, *w1l, *wd1h, *wd1l, *woh, *wol;
    bf16 *h0h, *h0l, *d0h, *d0l;
    float *h1p, *zp;
    cudaGetSymbolAddress((void**)&xh,  g_xh);   cudaGetSymbolAddress((void**)&xl,  g_xl);
    cudaGetSymbolAddress((void**)&w0h, g_w0h);  cudaGetSymbolAddress((void**)&w0l, g_w0l);
    cudaGetSymbolAddress((void**)&w1h, g_w1h);  cudaGetSymbolAddress((void**)&w1l, g_w1l);
    cudaGetSymbolAddress((void**)&wd1h, g_wd1h); cudaGetSymbolAddress((void**)&wd1l, g_wd1l);
    cudaGetSymbolAddress((void**)&woh, g_woh);  cudaGetSymbolAddress((void**)&wol, g_wol);
    cudaGetSymbolAddress((void**)&h0h, g_h0h);  cudaGetSymbolAddress((void**)&h0l, g_h0l);
    cudaGetSymbolAddress((void**)&d0h, g_d0h);  cudaGetSymbolAddress((void**)&d0l, g_d0l);
    cudaGetSymbolAddress((void**)&h1p, g_h1);   cudaGetSymbolAddress((void**)&zp,  g_z);

    cudaFuncSetAttribute(tc_gemm_k<true,  true,  1>,
                         cudaFuncAttributeMaxDynamicSharedMemorySize, TC_SMEM_TOTAL);
    cudaFuncSetAttribute(tc_gemm_k<true,  false, 0>,
                         cudaFuncAttributeMaxDynamicSharedMemorySize, TC_SMEM_TOTAL);
    cudaFuncSetAttribute(tc_gemm_k<false, false, 0>,
                         cudaFuncAttributeMaxDynamicSharedMemorySize, TC_SMEM_TOTAL);

    // 1. routing
    reset_counts_k<<<1, 32>>>();
    scatter_k<<<BSZ / 256, 256>>>(labels);

    // 2. conversions
    convert_act_k<<<(BSZ * DIN / 4) / 256, 256>>>(x, xh, xl, BSZ * DIN / 4);
    convert_wt_k<<<dim3(H0D / 32, DIN / 32, NC), dim3(32, 8)>>>(W_enc0, w0h, w0l, DIN, H0D);
    convert_wt_k<<<dim3(H1D / 32, H0D / 32, 1), dim3(32, 8)>>>(W_enc1, w1h, w1l, H0D, H1D);
    convert_wt_k<<<dim3(H0D / 32, H1D / 32, NC), dim3(32, 8)>>>(W_dec1, wd1h, wd1l, H1D, H0D);
    convert_wt_k<<<dim3(DIN / 32, H0D / 32, 1), dim3(32, 8)>>>(W_out, woh, wol, H0D, DIN);

    // 3. enc0 (grouped): h0 = relu(x @ W_enc0[c] + b) -> bf16 hi/lo
    tc_gemm_k<true, true, 1><<<dim3(H0D / TC_BN, BSZ / TC_BM, NC), TC_THREADS, TC_SMEM_TOTAL>>>(
        xh, xl, w0h, w0l, b_enc0, nullptr, h0h, h0l, BSZ, H0D, DIN);

    // 4. enc1: h1 = relu(h0 @ W_enc1 + b) -> fp32
    tc_gemm_k<true, false, 0><<<dim3(H1D / TC_BN, BSZ / TC_BM, 1), TC_THREADS, TC_SMEM_TOTAL>>>(
        h0h, h0l, w1h, w1l, b_enc1, h1p, nullptr, nullptr, BSZ, H1D, H0D);

    // 5. mu / logvar (SIMT fp32, straight into d_out)
    gemm_k<false, 0><<<dim3(LATD / BN, BSZ / BM), NTHREADS>>>(
        h1p, W_mu, b_mu, mu, nullptr, nullptr, LATD, H1D);
    gemm_k<false, 0><<<dim3(LATD / BN, BSZ / BM), NTHREADS>>>(
        h1p, W_logvar, b_logvar, logvar, nullptr, nullptr, LATD, H1D);

    // 6. reparameterize
    z_k<<<(BSZ * LATD) / 256, 256>>>(mu, logvar, eps, zp, BSZ * LATD);

    // 7. dec0 (SIMT, K=128): d0 = relu(z @ W_dec0 + b) -> bf16 hi/lo
    gemm_k<true, 1><<<dim3(H1D / BN, BSZ / BM), NTHREADS>>>(
        zp, W_dec0, b_dec0, nullptr, d0h, d0l, H1D, LATD);

    // 8. dec1 (grouped): d1 = relu(d0 @ W_dec1[c] + b) -> bf16 hi/lo (reuse h0 bufs)
    tc_gemm_k<true, true, 1><<<dim3(H0D / TC_BN, BSZ / TC_BM, NC), TC_THREADS, TC_SMEM_TOTAL>>>(
        d0h, d0l, wd1h, wd1l, b_dec1, nullptr, h0h, h0l, BSZ, H0D, H1D);

    // 9. out: recon = d1 @ W_out + b -> fp32
    tc_gemm_k<false, false, 0><<<dim3(DIN / TC_BN, BSZ / TC_BM, 1), TC_THREADS, TC_SMEM_TOTAL>>>(
        h0h, h0l, woh, wol, b_out, recon, nullptr, nullptr, BSZ, DIN, H0D);
}

// round 5
// speedup vs baseline: 2.0761x; 1.0358x over previous
#include <cuda_runtime.h>
#include <cuda_bf16.h>
#include <cstdint>
#include <math.h>

// ---------------------------------------------------------------------------
// Problem constants
// ---------------------------------------------------------------------------
#define BSZ   8192
#define DIN   2048
#define H0D   1024
#define H1D   512
#define LATD  128
#define NC    8

typedef __nv_bfloat16 bf16;

// ---------------------------------------------------------------------------
// Scratch (device globals)
// ---------------------------------------------------------------------------
__device__ bf16 g_xh [(size_t)BSZ * DIN];
__device__ bf16 g_xl [(size_t)BSZ * DIN];
__device__ bf16 g_w0h[(size_t)NC * H0D * DIN];   // enc0^T [C, H0, DIN]
__device__ bf16 g_w0l[(size_t)NC * H0D * DIN];
__device__ bf16 g_w1h[(size_t)H1D * H0D];        // enc1^T [H1, H0]
__device__ bf16 g_w1l[(size_t)H1D * H0D];
__device__ bf16 g_wd1h[(size_t)NC * H0D * H1D];  // dec1^T [C, H0, H1]
__device__ bf16 g_wd1l[(size_t)NC * H0D * H1D];
__device__ bf16 g_woh[(size_t)DIN * H0D];        // out^T [DIN, H0]
__device__ bf16 g_wol[(size_t)DIN * H0D];
__device__ bf16 g_h0h[(size_t)BSZ * H0D];        // h0, reused as d1
__device__ bf16 g_h0l[(size_t)BSZ * H0D];
__device__ bf16 g_d0h[(size_t)BSZ * H1D];
__device__ bf16 g_d0l[(size_t)BSZ * H1D];
__device__ float g_h1[(size_t)BSZ * H1D];
__device__ float g_z [(size_t)BSZ * LATD];
__device__ int   g_perm[NC * BSZ];
__device__ int   g_counts[NC];

// ---------------------------------------------------------------------------
// Routing
// ---------------------------------------------------------------------------
__global__ void reset_counts_k() {
    if (threadIdx.x < NC) g_counts[threadIdx.x] = 0;
}
__global__ void scatter_k(const int* __restrict__ labels) {
    int b = blockIdx.x * blockDim.x + threadIdx.x;
    if (b < BSZ) {
        int c = labels[b];
        int p = atomicAdd(&g_counts[c], 1);
        g_perm[c * BSZ + p] = b;
    }
}

// ---------------------------------------------------------------------------
// fp32 -> bf16 hi/lo split
// ---------------------------------------------------------------------------
__device__ __forceinline__ void split_bf16(float v, bf16& h, bf16& l) {
    h = __float2bfloat16_rn(v);
    l = __float2bfloat16_rn(v - __bfloat162float(h));
}

__global__ void convert_act_k(const float* __restrict__ X,
                              bf16* __restrict__ H, bf16* __restrict__ L, int n4) {
    int i = blockIdx.x * blockDim.x + threadIdx.x;
    if (i >= n4) return;
    float4 v = reinterpret_cast<const float4*>(X)[i];
    bf16 h0, h1, h2, h3, l0, l1, l2, l3;
    split_bf16(v.x, h0, l0); split_bf16(v.y, h1, l1);
    split_bf16(v.z, h2, l2); split_bf16(v.w, h3, l3);
    __nv_bfloat162 ph0 = __halves2bfloat162(h0, h1);
    __nv_bfloat162 ph1 = __halves2bfloat162(h2, h3);
    __nv_bfloat162 pl0 = __halves2bfloat162(l0, l1);
    __nv_bfloat162 pl1 = __halves2bfloat162(l2, l3);
    uint2 uh = make_uint2(*(uint32_t*)&ph0, *(uint32_t*)&ph1);
    uint2 ul = make_uint2(*(uint32_t*)&pl0, *(uint32_t*)&pl1);
    *reinterpret_cast<uint2*>(H + (size_t)i * 4) = uh;
    *reinterpret_cast<uint2*>(L + (size_t)i * 4) = ul;
}

// Weight convert + transpose: W [K,N] fp32 -> Th/Tl [N,K] bf16. grid.z = group.
__global__ void convert_wt_k(const float* __restrict__ W,
                             bf16* __restrict__ Th, bf16* __restrict__ Tl,
                             int K, int N) {
    __shared__ float tile[32][33];
    int g = blockIdx.z;
    const float* Wg = W + (size_t)g * K * N;
    bf16* Thg = Th + (size_t)g * N * K;
    bf16* Tlg = Tl + (size_t)g * N * K;
    int n0 = blockIdx.x * 32, k0 = blockIdx.y * 32;
    int tx = threadIdx.x, ty = threadIdx.y;   // 32 x 8
    #pragma unroll
    for (int i = 0; i < 4; i++)
        tile[ty + 8 * i][tx] = Wg[(size_t)(k0 + ty + 8 * i) * N + n0 + tx];
    __syncthreads();
    #pragma unroll
    for (int i = 0; i < 4; i++) {
        float v = tile[tx][ty + 8 * i];
        bf16 h, l;
        split_bf16(v, h, l);
        size_t o = (size_t)(n0 + ty + 8 * i) * K + k0 + tx;
        Thg[o] = h;
        Tlg[o] = l;
    }
}

// ---------------------------------------------------------------------------
// PTX wrappers
// ---------------------------------------------------------------------------
__device__ __forceinline__ uint32_t smem_u32(const void* p) {
    uint32_t a;
    asm("{ .reg .u64 t; cvta.to.shared.u64 t, %1; cvt.u32.u64 %0, t; }"
        : "=r"(a) : "l"(p));
    return a;
}

__device__ __forceinline__ void cp_async16(uint32_t saddr, const void* g, bool ok) {
    int sz = ok ? 16 : 0;
    asm volatile("cp.async.cg.shared.global [%0], [%1], 16, %2;"
                 :: "r"(saddr), "l"(g), "r"(sz));
}
#define CP_COMMIT() asm volatile("cp.async.commit_group;" ::: "memory")
#define CP_WAIT(n)  asm volatile("cp.async.wait_group %0;" :: "n"(n) : "memory")

__device__ __forceinline__ void ldsm_x4(uint32_t* r, uint32_t addr) {
    asm volatile("ldmatrix.sync.aligned.m8n8.x4.shared.b16 {%0,%1,%2,%3}, [%4];"
                 : "=r"(r[0]), "=r"(r[1]), "=r"(r[2]), "=r"(r[3]) : "r"(addr));
}

__device__ __forceinline__ void mma16816(float* c, const uint32_t* a, const uint32_t* b) {
    asm volatile(
        "mma.sync.aligned.m16n8k16.row.col.f32.bf16.bf16.f32 "
        "{%0,%1,%2,%3}, {%4,%5,%6,%7}, {%8,%9}, {%0,%1,%2,%3};"
        : "+f"(c[0]), "+f"(c[1]), "+f"(c[2]), "+f"(c[3])
        : "r"(a[0]), "r"(a[1]), "r"(a[2]), "r"(a[3]), "r"(b[0]), "r"(b[1]));
}

// ---------------------------------------------------------------------------
// mma.sync GEMM: 256x128x32 CTA tile, bf16x3 split, 3-stage cp.async pipeline.
// smem rows: 32 bf16 = 64B tight, XOR chunk swizzle c' = v ^ ((row>>1)&3)
// -> conflict-free ldmatrix + cp.async writes.
// ---------------------------------------------------------------------------
#define TC_BM 256
#define TC_BN 128
#define TC_KC 32
#define TC_THREADS 512
#define TC_NSTAGE 3

#define A_TILE_B (TC_BM * 64)          // 16384 B (per hi or lo tile)
#define B_TILE_B (TC_BN * 64)          // 8192 B
#define STAGE_B  (2 * A_TILE_B + 2 * B_TILE_B)   // 49152 B: [Ah][Al][Bh][Bl]
#define OFF_AH 0
#define OFF_AL A_TILE_B
#define OFF_BH (2 * A_TILE_B)
#define OFF_BL (2 * A_TILE_B + B_TILE_B)
#define SM_ROWS_OFF (TC_NSTAGE * STAGE_B)
#define TC_SMEM_TOTAL (SM_ROWS_OFF + TC_BM * 4)  // 148480 B

__device__ __forceinline__ uint32_t swz_off(int row, int v) {
    return (uint32_t)(row * 64 + ((v ^ ((row >> 1) & 3)) << 4));
}

template <bool GROUPED>
__device__ __forceinline__ void tc_load_stage(
    uint32_t stage_base, const int* __restrict__ rows, int tid, int k0,
    const bf16* __restrict__ Ah, const bf16* __restrict__ Al,
    const bf16* __restrict__ Bh, const bf16* __restrict__ Bl,
    int m0, int n0, int K)
{
    // 3072 x 16B ops: A 2048 (2 tiles x 256 rows x 4 chunks), B 1024
    #pragma unroll
    for (int t = 0; t < 6; t++) {
        int idx = tid + t * TC_THREADS;
        if (idx < 2048) {
            int tile = idx >> 10;
            int rem  = idx & 1023;
            int row  = rem >> 2;
            int v    = rem & 3;
            int gr = GROUPED ? rows[row] : (m0 + row);
            bool ok = !GROUPED || (gr >= 0);
            const bf16* src = tile ? Al : Ah;
            cp_async16(stage_base + (tile ? OFF_AL : OFF_AH) + swz_off(row, v),
                       src + ((size_t)(ok ? gr : 0) * K + k0 + v * 8), ok);
        } else {
            int j    = idx - 2048;
            int tile = j >> 9;
            int rem  = j & 511;
            int row  = rem >> 2;
            int v    = rem & 3;
            const bf16* src = tile ? Bl : Bh;
            cp_async16(stage_base + (tile ? OFF_BL : OFF_BH) + swz_off(row, v),
                       src + ((size_t)(n0 + row) * K + k0 + v * 8), true);
        }
    }
}

// OUTMODE: 0 = fp32 Out, 1 = bf16 hi/lo Oh/Ol
template <bool RELU, bool GROUPED, int OUTMODE>
__global__ void __launch_bounds__(TC_THREADS, 1)
tc_gemm_k(const bf16* __restrict__ Ah, const bf16* __restrict__ Al,
          const bf16* __restrict__ Bhg, const bf16* __restrict__ Blg,
          const float* __restrict__ biasg,
          float* __restrict__ OutF,
          bf16* __restrict__ Oh, bf16* __restrict__ Ol,
          int M, int N, int K)
{
    extern __shared__ char smem[];
    const int tid  = threadIdx.x;
    const int wid  = tid >> 5;
    const int lane = tid & 31;
    const int wm   = wid >> 2;   // 0..3 (64-row band)
    const int wn   = wid & 3;    // 0..3 (32-col band)
    const int g    = GROUPED ? blockIdx.z : 0;
    const int m0   = blockIdx.y * TC_BM;
    if (GROUPED) {
        if (m0 >= g_counts[g]) return;
    }
    const int n0 = blockIdx.x * TC_BN;
    uint32_t sb = smem_u32(smem);
    int* rows_s = reinterpret_cast<int*>(smem + SM_ROWS_OFF);

    if (GROUPED) {
        if (tid < TC_BM) {
            int cnt = g_counts[g];
            int r = m0 + tid;
            rows_s[tid] = (r < cnt) ? g_perm[g * BSZ + r] : -1;
        }
        __syncthreads();
    }

    const bf16* Bh = Bhg + (GROUPED ? (size_t)g * N * K : 0);
    const bf16* Bl = Blg + (GROUPED ? (size_t)g * N * K : 0);

    float acc[4][4][4];
    #pragma unroll
    for (int i = 0; i < 4; i++)
        #pragma unroll
        for (int j = 0; j < 4; j++)
            #pragma unroll
            for (int q = 0; q < 4; q++) acc[i][j][q] = 0.f;

    const int nchunks = K / TC_KC;

    // prologue: stages 0, 1
    tc_load_stage<GROUPED>(sb + 0 * STAGE_B, rows_s, tid, 0, Ah, Al, Bh, Bl, m0, n0, K);
    CP_COMMIT();
    tc_load_stage<GROUPED>(sb + 1 * STAGE_B, rows_s, tid, TC_KC, Ah, Al, Bh, Bl, m0, n0, K);
    CP_COMMIT();

    int stage = 0;
    for (int i = 0; i < nchunks; i++) {
        if (i + 1 < nchunks) { CP_WAIT(1); } else { CP_WAIT(0); }
        __syncthreads();   // stage i data visible; all warps done with stage i-1

        // prefetch stage i+2 into the buffer freed at iteration i-1
        if (i + 2 < nchunks) {
            int ps = stage + 2; if (ps >= TC_NSTAGE) ps -= TC_NSTAGE;
            tc_load_stage<GROUPED>(sb + ps * STAGE_B, rows_s, tid, (i + 2) * TC_KC,
                                   Ah, Al, Bh, Bl, m0, n0, K);
            CP_COMMIT();
        }

        uint32_t st = sb + stage * STAGE_B;
        #pragma unroll
        for (int kk = 0; kk < 2; kk++) {
            const int vb = kk * 2 + (lane >> 4);
            // B fragments
            uint32_t bh[8], bl[8];
            #pragma unroll
            for (int p = 0; p < 2; p++) {
                int brow = wn * 32 + p * 16 + (lane & 15);
                uint32_t r[4];
                ldsm_x4(r, st + OFF_BH + swz_off(brow, vb));
                bh[4 * p + 0] = r[0]; bh[4 * p + 1] = r[2];
                bh[4 * p + 2] = r[1]; bh[4 * p + 3] = r[3];
                ldsm_x4(r, st + OFF_BL + swz_off(brow, vb));
                bl[4 * p + 0] = r[0]; bl[4 * p + 1] = r[2];
                bl[4 * p + 2] = r[1]; bl[4 * p + 3] = r[3];
            }
            // A hi fragments
            uint32_t a[4][4];
            #pragma unroll
            for (int mt = 0; mt < 4; mt++) {
                int arow = wm * 64 + mt * 16 + (lane & 15);
                ldsm_x4(a[mt], st + OFF_AH + swz_off(arow, vb));
            }
            #pragma unroll
            for (int mt = 0; mt < 4; mt++)
                #pragma unroll
                for (int nt = 0; nt < 4; nt++) {
                    mma16816(acc[mt][nt], a[mt], &bh[2 * nt]);
                    mma16816(acc[mt][nt], a[mt], &bl[2 * nt]);
                }
            // A lo fragments (overwrite)
            #pragma unroll
            for (int mt = 0; mt < 4; mt++) {
                int arow = wm * 64 + mt * 16 + (lane & 15);
                ldsm_x4(a[mt], st + OFF_AL + swz_off(arow, vb));
            }
            #pragma unroll
            for (int mt = 0; mt < 4; mt++)
                #pragma unroll
                for (int nt = 0; nt < 4; nt++)
                    mma16816(acc[mt][nt], a[mt], &bh[2 * nt]);
        }
        stage = stage + 1; if (stage >= TC_NSTAGE) stage = 0;
    }

    // Epilogue
    const float* bias = biasg + (GROUPED ? (size_t)g * N : 0);
    #pragma unroll
    for (int mt = 0; mt < 4; mt++) {
        #pragma unroll
        for (int half = 0; half < 2; half++) {
            int rloc = wm * 64 + mt * 16 + (lane >> 2) + half * 8;
            int gm = GROUPED ? rows_s[rloc] : (m0 + rloc);
            if (GROUPED && gm < 0) continue;
            #pragma unroll
            for (int nt = 0; nt < 4; nt++) {
                int col = n0 + wn * 32 + nt * 8 + 2 * (lane & 3);
                float c0 = acc[mt][nt][2 * half + 0] + bias[col];
                float c1 = acc[mt][nt][2 * half + 1] + bias[col + 1];
                if (RELU) { c0 = fmaxf(c0, 0.f); c1 = fmaxf(c1, 0.f); }
                if (OUTMODE == 0) {
                    *reinterpret_cast<float2*>(OutF + (size_t)gm * N + col) =
                        make_float2(c0, c1);
                } else {
                    bf16 h0, h1, l0, l1;
                    split_bf16(c0, h0, l0);
                    split_bf16(c1, h1, l1);
                    __nv_bfloat162 ph = __halves2bfloat162(h0, h1);
                    __nv_bfloat162 pl = __halves2bfloat162(l0, l1);
                    *reinterpret_cast<uint32_t*>(Oh + (size_t)gm * N + col) =
                        *reinterpret_cast<uint32_t*>(&ph);
                    *reinterpret_cast<uint32_t*>(Ol + (size_t)gm * N + col) =
                        *reinterpret_cast<uint32_t*>(&pl);
                }
            }
        }
    }
}

// ---------------------------------------------------------------------------
// SIMT fp32 GEMM (small layers). OUTMODE: 0 = fp32, 1 = bf16 hi/lo
// ---------------------------------------------------------------------------
#define BM 128
#define BN 128
#define BK 16
#define TM 8
#define TN 8
#define NTHREADS 256

template <bool RELU, int OUTMODE>
__global__ __launch_bounds__(NTHREADS)
void gemm_k(const float* __restrict__ A, const float* __restrict__ W,
            const float* __restrict__ bias, float* __restrict__ Out,
            bf16* __restrict__ Oh, bf16* __restrict__ Ol,
            int N, int K) {
    __shared__ float As[BK][BM];
    __shared__ float Bs[BK][BN];

    const int tid = threadIdx.x;
    const int tx = tid & 15;
    const int ty = tid >> 4;
    const int m0 = blockIdx.y * BM;
    const int n0 = blockIdx.x * BN;

    const float* Aptr = A + (size_t)m0 * K;
    const float* Wptr = W + n0;

    float acc[TM][TN];
    #pragma unroll
    for (int i = 0; i < TM; i++)
        #pragma unroll
        for (int j = 0; j < TN; j++) acc[i][j] = 0.f;

    for (int k0 = 0; k0 < K; k0 += BK) {
        #pragma unroll
        for (int i = 0; i < 2; i++) {
            int idx = tid + i * NTHREADS;
            int row = idx >> 2;
            int c4  = idx & 3;
            float4 v = *reinterpret_cast<const float4*>(Aptr + (size_t)row * K + k0 + c4 * 4);
            As[c4 * 4 + 0][row] = v.x;
            As[c4 * 4 + 1][row] = v.y;
            As[c4 * 4 + 2][row] = v.z;
            As[c4 * 4 + 3][row] = v.w;
        }
        #pragma unroll
        for (int i = 0; i < 2; i++) {
            int idx = tid + i * NTHREADS;
            int row = idx >> 5;
            int c4  = idx & 31;
            float4 v = *reinterpret_cast<const float4*>(Wptr + (size_t)(k0 + row) * N + c4 * 4);
            *reinterpret_cast<float4*>(&Bs[row][c4 * 4]) = v;
        }
        __syncthreads();

        #pragma unroll
        for (int k = 0; k < BK; k++) {
            float ra[TM], rb[TN];
            #pragma unroll
            for (int i = 0; i < TM; i++) ra[i] = As[k][ty * TM + i];
            #pragma unroll
            for (int j = 0; j < TN; j++) rb[j] = Bs[k][tx * TN + j];
            #pragma unroll
            for (int i = 0; i < TM; i++)
                #pragma unroll
                for (int j = 0; j < TN; j++)
                    acc[i][j] = fmaf(ra[i], rb[j], acc[i][j]);
        }
        __syncthreads();
    }

    #pragma unroll
    for (int i = 0; i < TM; i++) {
        int m = m0 + ty * TM + i;
        size_t obase = (size_t)m * N + n0 + tx * TN;
        #pragma unroll
        for (int j = 0; j < TN; j++) {
            float v = acc[i][j] + bias[n0 + tx * TN + j];
            if (RELU) v = fmaxf(v, 0.f);
            acc[i][j] = v;
        }
        if (OUTMODE == 0) {
            #pragma unroll
            for (int j4 = 0; j4 < 2; j4++)
                *reinterpret_cast<float4*>(Out + obase + j4 * 4) =
                    make_float4(acc[i][j4*4], acc[i][j4*4+1], acc[i][j4*4+2], acc[i][j4*4+3]);
        } else {
            uint32_t* dh = reinterpret_cast<uint32_t*>(Oh + obase);
            uint32_t* dl = reinterpret_cast<uint32_t*>(Ol + obase);
            #pragma unroll
            for (int q = 0; q < 4; q++) {
                bf16 h0, h1, l0, l1;
                split_bf16(acc[i][2*q],   h0, l0);
                split_bf16(acc[i][2*q+1], h1, l1);
                __nv_bfloat162 ph = __halves2bfloat162(h0, h1);
                __nv_bfloat162 pl = __halves2bfloat162(l0, l1);
                dh[q] = *reinterpret_cast<uint32_t*>(&ph);
                dl[q] = *reinterpret_cast<uint32_t*>(&pl);
            }
        }
    }
}

// ---------------------------------------------------------------------------
// Reparameterize
// ---------------------------------------------------------------------------
__global__ void z_k(const float* __restrict__ mu, const float* __restrict__ logvar,
                    const float* __restrict__ eps, float* __restrict__ z, int n) {
    int i = blockIdx.x * blockDim.x + threadIdx.x;
    if (i < n) z[i] = fmaf(eps[i], expf(0.5f * logvar[i]), mu[i]);
}

// ---------------------------------------------------------------------------
// Launcher
// ---------------------------------------------------------------------------
extern "C" void kernel_launch(void* const* d_in, const int* in_sizes, int n_in,
                              void* d_out, int out_size) {
    const float* x        = (const float*)d_in[0];
    const int*   labels   = (const int*)  d_in[1];
    const float* eps      = (const float*)d_in[2];
    const float* W_enc0   = (const float*)d_in[3];
    const float* b_enc0   = (const float*)d_in[4];
    const float* W_enc1   = (const float*)d_in[5];
    const float* b_enc1   = (const float*)d_in[6];
    const float* W_mu     = (const float*)d_in[7];
    const float* b_mu     = (const float*)d_in[8];
    const float* W_logvar = (const float*)d_in[9];
    const float* b_logvar = (const float*)d_in[10];
    const float* W_dec0   = (const float*)d_in[11];
    const float* b_dec0   = (const float*)d_in[12];
    const float* W_dec1   = (const float*)d_in[13];
    const float* b_dec1   = (const float*)d_in[14];
    const float* W_out    = (const float*)d_in[15];
    const float* b_out    = (const float*)d_in[16];

    float* recon  = (float*)d_out;
    float* mu     = recon + (size_t)BSZ * DIN;
    float* logvar = mu    + (size_t)BSZ * LATD;

    bf16 *xh, *xl, *w0h, *w0l, *w1h, *w1l, *wd1h, *wd1l, *woh, *wol;
    bf16 *h0h, *h0l, *d0h, *d0l;
    float *h1p, *zp;
    cudaGetSymbolAddress((void**)&xh,  g_xh);   cudaGetSymbolAddress((void**)&xl,  g_xl);
    cudaGetSymbolAddress((void**)&w0h, g_w0h);  cudaGetSymbolAddress((void**)&w0l, g_w0l);
    cudaGetSymbolAddress((void**)&w1h, g_w1h);  cudaGetSymbolAddress((void**)&w1l, g_w1l);
    cudaGetSymbolAddress((void**)&wd1h, g_wd1h); cudaGetSymbolAddress((void**)&wd1l, g_wd1l);
    cudaGetSymbolAddress((void**)&woh, g_woh);  cudaGetSymbolAddress((void**)&wol, g_wol);
    cudaGetSymbolAddress((void**)&h0h, g_h0h);  cudaGetSymbolAddress((void**)&h0l, g_h0l);
    cudaGetSymbolAddress((void**)&d0h, g_d0h);  cudaGetSymbolAddress((void**)&d0l, g_d0l);
    cudaGetSymbolAddress((void**)&h1p, g_h1);   cudaGetSymbolAddress((void**)&zp,  g_z);

    cudaFuncSetAttribute(tc_gemm_k<true,  true,  1>,
                         cudaFuncAttributeMaxDynamicSharedMemorySize, TC_SMEM_TOTAL);
    cudaFuncSetAttribute(tc_gemm_k<true,  false, 0>,
                         cudaFuncAttributeMaxDynamicSharedMemorySize, TC_SMEM_TOTAL);
    cudaFuncSetAttribute(tc_gemm_k<false, false, 0>,
                         cudaFuncAttributeMaxDynamicSharedMemorySize, TC_SMEM_TOTAL);

    // 1. routing
    reset_counts_k<<<1, 32>>>();
    scatter_k<<<BSZ / 256, 256>>>(labels);

    // 2. conversions
    convert_act_k<<<(BSZ * DIN / 4) / 256, 256>>>(x, xh, xl, BSZ * DIN / 4);
    convert_wt_k<<<dim3(H0D / 32, DIN / 32, NC), dim3(32, 8)>>>(W_enc0, w0h, w0l, DIN, H0D);
    convert_wt_k<<<dim3(H1D / 32, H0D / 32, 1), dim3(32, 8)>>>(W_enc1, w1h, w1l, H0D, H1D);
    convert_wt_k<<<dim3(H0D / 32, H1D / 32, NC), dim3(32, 8)>>>(W_dec1, wd1h, wd1l, H1D, H0D);
    convert_wt_k<<<dim3(DIN / 32, H0D / 32, 1), dim3(32, 8)>>>(W_out, woh, wol, H0D, DIN);

    // 3. enc0 (grouped): h0 = relu(x @ W_enc0[c] + b) -> bf16 hi/lo
    tc_gemm_k<true, true, 1><<<dim3(H0D / TC_BN, BSZ / TC_BM, NC), TC_THREADS, TC_SMEM_TOTAL>>>(
        xh, xl, w0h, w0l, b_enc0, nullptr, h0h, h0l, BSZ, H0D, DIN);

    // 4. enc1: h1 = relu(h0 @ W_enc1 + b) -> fp32
    tc_gemm_k<true, false, 0><<<dim3(H1D / TC_BN, BSZ / TC_BM, 1), TC_THREADS, TC_SMEM_TOTAL>>>(
        h0h, h0l, w1h, w1l, b_enc1, h1p, nullptr, nullptr, BSZ, H1D, H0D);

    // 5. mu / logvar (SIMT fp32, straight into d_out)
    gemm_k<false, 0><<<dim3(LATD / BN, BSZ / BM), NTHREADS>>>(
        h1p, W_mu, b_mu, mu, nullptr, nullptr, LATD, H1D);
    gemm_k<false, 0><<<dim3(LATD / BN, BSZ / BM), NTHREADS>>>(
        h1p, W_logvar, b_logvar, logvar, nullptr, nullptr, LATD, H1D);

    // 6. reparameterize
    z_k<<<(BSZ * LATD) / 256, 256>>>(mu, logvar, eps, zp, BSZ * LATD);

    // 7. dec0 (SIMT, K=128): d0 = relu(z @ W_dec0 + b) -> bf16 hi/lo
    gemm_k<true, 1><<<dim3(H1D / BN, BSZ / BM), NTHREADS>>>(
        zp, W_dec0, b_dec0, nullptr, d0h, d0l, H1D, LATD);

    // 8. dec1 (grouped): d1 = relu(d0 @ W_dec1[c] + b) -> bf16 hi/lo (reuse h0 bufs)
    tc_gemm_k<true, true, 1><<<dim3(H0D / TC_BN, BSZ / TC_BM, NC), TC_THREADS, TC_SMEM_TOTAL>>>(
        d0h, d0l, wd1h, wd1l, b_dec1, nullptr, h0h, h0l, BSZ, H0D, H1D);

    // 9. out: recon = d1 @ W_out + b -> fp32
    tc_gemm_k<false, false, 0><<<dim3(DIN / TC_BN, BSZ / TC_BM, 1), TC_THREADS, TC_SMEM_TOTAL>>>(
        h0h, h0l, woh, wol, b_out, recon, nullptr, nullptr, BSZ, DIN, H0D);
}